// round 10
// baseline (speedup 1.0000x reference)
#include <cuda_runtime.h>
#include <math.h>

// ---------------------------------------------------------------------------
// Helpers
// ---------------------------------------------------------------------------
__device__ __forceinline__ float det3f(float a0, float a1, float a2,
                                       float b0, float b1, float b2,
                                       float c0, float c1, float c2) {
    return a0 * (b1 * c2 - b2 * c1)
         - a1 * (b0 * c2 - b2 * c0)
         + a2 * (b0 * c1 - b1 * c0);
}

__device__ __forceinline__ void cross4f(const float a[4], const float b[4],
                                        const float c[4], float q[4]) {
    q[0] =  det3f(a[1], a[2], a[3], b[1], b[2], b[3], c[1], c[2], c[3]);
    q[1] = -det3f(a[0], a[2], a[3], b[0], b[2], b[3], c[0], c[2], c[3]);
    q[2] =  det3f(a[0], a[1], a[3], b[0], b[1], b[3], c[0], c[1], c[3]);
    q[3] = -det3f(a[0], a[1], a[2], b[0], b[1], b[2], c[0], c[1], c[2]);
}

// Best null-vector of (N - lam*I): try all four row-triples, keep max-norm.
__device__ __forceinline__ void null4(const float N0[4], const float N1[4],
                                      const float N2[4], const float N3[4],
                                      float lam, float q[4]) {
    float M0[4] = {N0[0] - lam, N0[1], N0[2], N0[3]};
    float M1[4] = {N1[0], N1[1] - lam, N1[2], N1[3]};
    float M2[4] = {N2[0], N2[1], N2[2] - lam, N2[3]};
    float M3[4] = {N3[0], N3[1], N3[2], N3[3] - lam};
    float cand[4];
    float best;

    cross4f(M1, M2, M3, cand);
    best = cand[0]*cand[0] + cand[1]*cand[1] + cand[2]*cand[2] + cand[3]*cand[3];
    q[0] = cand[0]; q[1] = cand[1]; q[2] = cand[2]; q[3] = cand[3];

    cross4f(M0, M2, M3, cand);
    {
        float n2 = cand[0]*cand[0] + cand[1]*cand[1] + cand[2]*cand[2] + cand[3]*cand[3];
        if (n2 > best) { best = n2; q[0]=cand[0]; q[1]=cand[1]; q[2]=cand[2]; q[3]=cand[3]; }
    }
    cross4f(M0, M1, M3, cand);
    {
        float n2 = cand[0]*cand[0] + cand[1]*cand[1] + cand[2]*cand[2] + cand[3]*cand[3];
        if (n2 > best) { best = n2; q[0]=cand[0]; q[1]=cand[1]; q[2]=cand[2]; q[3]=cand[3]; }
    }
    cross4f(M0, M1, M2, cand);
    {
        float n2 = cand[0]*cand[0] + cand[1]*cand[1] + cand[2]*cand[2] + cand[3]*cand[3];
        if (n2 > best) { best = n2; q[0]=cand[0]; q[1]=cand[1]; q[2]=cand[2]; q[3]=cand[3]; }
    }
}

// One Rayleigh-quotient refinement: normalize q, lam = q^T N q, re-extract.
__device__ __forceinline__ void rayleigh_refine(const float N0[4], const float N1[4],
                                                const float N2[4], const float N3[4],
                                                float q[4]) {
    float n2 = q[0]*q[0] + q[1]*q[1] + q[2]*q[2] + q[3]*q[3];
    if (n2 > 1e-30f) {
        float inv = rsqrtf(n2);
        float w = q[0]*inv, x = q[1]*inv, y = q[2]*inv, z = q[3]*inv;
        float t0 = N0[0]*w + N0[1]*x + N0[2]*y + N0[3]*z;
        float t1 = N1[0]*w + N1[1]*x + N1[2]*y + N1[3]*z;
        float t2 = N2[0]*w + N2[1]*x + N2[2]*y + N2[3]*z;
        float t3 = N3[0]*w + N3[1]*x + N3[2]*y + N3[3]*z;
        float lam = w*t0 + x*t1 + y*t2 + z*t3;
        null4(N0, N1, N2, N3, lam, q);
    }
}

#define ABLK 128

// ---------------------------------------------------------------------------
// Phase: Kabsch + NeRF (unchanged proven config: Newton 14 + 2x Rayleigh)
// ---------------------------------------------------------------------------
__device__ __forceinline__ void phase_kabsch_nerf(
    const float* __restrict__ fixedp, const float* __restrict__ mobilep,
    const float* __restrict__ prev, const float* __restrict__ bl,
    const float* __restrict__ ban, const float* __restrict__ dih,
    float* __restrict__ out_next, float (*sAT)[13], int res, int tid, int N)
{
    if (res >= N) return;

    {
        const float* fp = fixedp  + (size_t)res * 9;
        const float* mp = mobilep + (size_t)res * 9;
        float f0x = fp[0], f0y = fp[1], f0z = fp[2];
        float f1x = fp[3], f1y = fp[4], f1z = fp[5];
        float f2x = fp[6], f2y = fp[7], f2z = fp[8];
        float m0x = mp[0], m0y = mp[1], m0z = mp[2];
        float m1x = mp[3], m1y = mp[4], m1z = mp[5];
        float m2x = mp[6], m2y = mp[7], m2z = mp[8];

        const float third = 1.0f / 3.0f;
        float fcx = (f0x + f1x + f2x) * third;
        float fcy = (f0y + f1y + f2y) * third;
        float fcz = (f0z + f1z + f2z) * third;
        float mcx = (m0x + m1x + m2x) * third;
        float mcy = (m0y + m1y + m2y) * third;
        float mcz = (m0z + m1z + m2z) * third;

        float a0x = m0x - mcx, a0y = m0y - mcy, a0z = m0z - mcz;
        float a1x = m1x - mcx, a1y = m1y - mcy, a1z = m1z - mcz;
        float a2x = m2x - mcx, a2y = m2y - mcy, a2z = m2z - mcz;
        float b0x = f0x - fcx, b0y = f0y - fcy, b0z = f0z - fcz;
        float b1x = f1x - fcx, b1y = f1y - fcy, b1z = f1z - fcz;
        float b2x = f2x - fcx, b2y = f2y - fcy, b2z = f2z - fcz;

        float Sxx = a0x*b0x + a1x*b1x + a2x*b2x;
        float Sxy = a0x*b0y + a1x*b1y + a2x*b2y;
        float Sxz = a0x*b0z + a1x*b1z + a2x*b2z;
        float Syx = a0y*b0x + a1y*b1x + a2y*b2x;
        float Syy = a0y*b0y + a1y*b1y + a2y*b2y;
        float Syz = a0y*b0z + a1y*b1z + a2y*b2z;
        float Szx = a0z*b0x + a1z*b1x + a2z*b2x;
        float Szy = a0z*b0y + a1z*b1y + a2z*b2y;
        float Szz = a0z*b0z + a1z*b1z + a2z*b2z;

        float N0[4] = {Sxx + Syy + Szz, Syz - Szy, Szx - Sxz, Sxy - Syx};
        float N1[4] = {N0[1], Sxx - Syy - Szz, Sxy + Syx, Szx + Sxz};
        float N2[4] = {N0[2], N1[2], -Sxx + Syy - Szz, Syz + Szy};
        float N3[4] = {N0[3], N1[3], N2[3], -Sxx - Syy + Szz};

        float fro2 = Sxx*Sxx + Sxy*Sxy + Sxz*Sxz
                   + Syx*Syx + Syy*Syy + Syz*Syz
                   + Szx*Szx + Szy*Szy + Szz*Szz;
        float c2 = -2.0f * fro2;
        float c1 = -8.0f * det3f(Sxx, Sxy, Sxz, Syx, Syy, Syz, Szx, Szy, Szz);
        float cof[4];
        cross4f(N1, N2, N3, cof);
        float c0 = N0[0]*cof[0] + N0[1]*cof[1] + N0[2]*cof[2] + N0[3]*cof[3];

        // Newton from upper bound sqrt(-2 c2). 14 iterations: proven floor (R3).
        float lam = sqrtf(fmaxf(-2.0f * c2, 0.0f));
        #pragma unroll 1
        for (int it = 0; it < 14; ++it) {
            float l2 = lam * lam;
            float fv = l2 * l2 + c2 * l2 + c1 * lam + c0;
            float fd = 4.0f * l2 * lam + 2.0f * c2 * lam + c1;
            fd = (fabsf(fd) > 1e-12f) ? fd : 1e-12f;
            lam -= __fdividef(fv, fd);
        }

        float q[4];
        null4(N0, N1, N2, N3, lam, q);
        rayleigh_refine(N0, N1, N2, N3, q);
        rayleigh_refine(N0, N1, N2, N3, q);

        float n2 = q[0]*q[0] + q[1]*q[1] + q[2]*q[2] + q[3]*q[3];
        if (n2 < 1e-30f) { q[0] = 1.0f; q[1] = q[2] = q[3] = 0.0f; n2 = 1.0f; }
        float inv = rsqrtf(n2);
        float w = q[0]*inv, x = q[1]*inv, y = q[2]*inv, z = q[3]*inv;

        float A00 = 1.0f - 2.0f*(y*y + z*z);
        float A01 = 2.0f*(x*y - w*z);
        float A02 = 2.0f*(x*z + w*y);
        float A10 = 2.0f*(x*y + w*z);
        float A11 = 1.0f - 2.0f*(x*x + z*z);
        float A12 = 2.0f*(y*z - w*x);
        float A20 = 2.0f*(x*z - w*y);
        float A21 = 2.0f*(y*z + w*x);
        float A22 = 1.0f - 2.0f*(x*x + y*y);

        float* s = sAT[tid];
        s[0] = A00; s[1] = A01; s[2] = A02;
        s[3] = A10; s[4] = A11; s[5] = A12;
        s[6] = A20; s[7] = A21; s[8] = A22;
        s[9]  = fcx - (A00*mcx + A01*mcy + A02*mcz);
        s[10] = fcy - (A10*mcx + A11*mcy + A12*mcz);
        s[11] = fcz - (A20*mcx + A21*mcy + A22*mcz);
    }

    {
        const float* p = prev + (size_t)res * 9;
        float p0x = p[0], p0y = p[1], p0z = p[2];
        float p1x = p[3], p1y = p[4], p1z = p[5];
        float p2x = p[6], p2y = p[7], p2z = p[8];

        float bcx = p1x - p2x, bcy = p1y - p2y, bcz = p1z - p2z;
        float invn = 1.0f / (sqrtf(bcx*bcx + bcy*bcy + bcz*bcz) + 1e-6f);
        bcx *= invn; bcy *= invn; bcz *= invn;

        float ux = p1x - p0x, uy = p1y - p0y, uz = p1z - p0z;
        float bax = uy*bcz - uz*bcy;
        float bay = uz*bcx - ux*bcz;
        float baz = ux*bcy - uy*bcx;
        invn = 1.0f / (sqrtf(bax*bax + bay*bay + baz*baz) + 1e-6f);
        bax *= invn; bay *= invn; baz *= invn;

        float m1x = bay*bcz - baz*bcy;
        float m1y = baz*bcx - bax*bcz;
        float m1z = bax*bcy - bay*bcx;

        float L = bl[res], A = ban[res], D = dih[res];
        float sA = sinf(A), cA = cosf(A);
        float sD = sinf(D), cD = cosf(D);
        float d1 = L * cA;
        float d2 = L * sA * cD;
        float d3 = -L * sA * sD;

        float* o = out_next + (size_t)res * 3;
        o[0] = p2x + bcx*d1 + m1x*d2 + bax*d3;
        o[1] = p2y + bcy*d1 + m1y*d2 + bay*d3;
        o[2] = p2z + bcz*d1 + m1z*d2 + baz*d3;
    }
}

__device__ __forceinline__ void phase_transform(
    const float* __restrict__ coords, float* __restrict__ out_aligned,
    const float (*sAT)[13], int base, int tid, int N)
{
    int nres = N - base;
    if (nres > ABLK) nres = ABLK;
    const int atomsTotal = nres * 15;
    #pragma unroll
    for (int k = 0; k < 15; ++k) {
        int a = k * ABLK + tid;
        if (a < atomsTotal) {
            int rl = a / 15;
            const float* cp = coords + (size_t)base * 45 + a * 3;
            float px = __ldcs(cp + 0);
            float py = __ldcs(cp + 1);
            float pz = __ldcs(cp + 2);
            const float* s = sAT[rl];
            float ox = s[0]*px + s[1]*py + s[2]*pz + s[9];
            float oy = s[3]*px + s[4]*py + s[5]*pz + s[10];
            float oz = s[6]*px + s[7]*py + s[8]*pz + s[11];
            float* op = out_aligned + (size_t)base * 45 + a * 3;
            __stcs(op + 0, ox);
            __stcs(op + 1, oy);
            __stcs(op + 2, oz);
        }
    }
}

// ---------------------------------------------------------------------------
// Chi RBF, two warp-coherent passes (no data-dependent branches):
//  pass 1: coalesced float4 zero-fill of all 18 groups per row.
//  pass 2: per row, write the 5 consecutive groups that can contain nonzero
//          bins (bins kc+-7 where kc = nearest bin; all other bins underflow
//          fp32 exp to exactly 0, identical to the fp32 reference).
// Requires __syncthreads between passes (cross-thread same-address ordering).
// ---------------------------------------------------------------------------
__device__ __forceinline__ void phase_chi_zero(
    float4* __restrict__ out_chi, int base, int tid, int N)
{
    float4* chi = out_chi + (size_t)base * 72;
    int nres = N - base;
    if (nres > ABLK) nres = ABLK;
    const int groupsTotal = nres * 72;
    const float4 z = make_float4(0.0f, 0.0f, 0.0f, 0.0f);
    #pragma unroll 4
    for (int v = tid; v < groupsTotal; v += ABLK) {
        __stcs(&chi[v], z);
    }
}

__device__ __forceinline__ void phase_chi_active(
    const float* __restrict__ sDeg, float4* __restrict__ out_chi,
    int base, int tid, int N)
{
    float4* chi = out_chi + (size_t)base * 72;
    int nres = N - base;
    if (nres > ABLK) nres = ABLK;
    const int rowsTotal = nres * 4;

    #pragma unroll
    for (int j = 0; j < 4; ++j) {
        int rowl = tid + j * ABLK;        // 0..511
        if (rowl < rowsTotal) {
            float deg = sDeg[rowl];
            // nearest bin index kc = floor((deg+182.5)/5), in 0..72 (72 == 0 circularly)
            int kc = (int)floorf((deg + 182.5f) * 0.2f);
            // first group of the 5-group window: floor((kc-7)/4) mod 18,
            // computed in non-negative space: (kc+65)/4 in 16..34
            int g0u = (kc + 65) >> 2;
            float4* rowp = chi + rowl * 18;
            #pragma unroll
            for (int t = 0; t < 5; ++t) {
                int g = g0u + t;          // 16..38
                g -= (g >= 36) ? 36 : ((g >= 18) ? 18 : 0);
                float cbase = -180.0f + 20.0f * (float)g;
                float r0, r1, r2, r3;
                {
                    float ad = fabsf(deg - cbase);
                    float dw = fminf(ad, 360.0f - ad);
                    r0 = __expf(-0.08f * dw * dw);
                }
                {
                    float ad = fabsf(deg - (cbase + 5.0f));
                    float dw = fminf(ad, 360.0f - ad);
                    r1 = __expf(-0.08f * dw * dw);
                }
                {
                    float ad = fabsf(deg - (cbase + 10.0f));
                    float dw = fminf(ad, 360.0f - ad);
                    r2 = __expf(-0.08f * dw * dw);
                }
                {
                    float ad = fabsf(deg - (cbase + 15.0f));
                    float dw = fminf(ad, 360.0f - ad);
                    r3 = __expf(-0.08f * dw * dw);
                }
                __stcs(&rowp[g], make_float4(r0, r1, r2, r3));
            }
        }
    }
}

// ---------------------------------------------------------------------------
// Fused kernel with phase-parity scheduling.
// ---------------------------------------------------------------------------
__global__ void __launch_bounds__(ABLK) fused_kernel(
    const float* __restrict__ fixedp,
    const float* __restrict__ mobilep,
    const float* __restrict__ coords,
    const float* __restrict__ prev,
    const float* __restrict__ bl,
    const float* __restrict__ ban,
    const float* __restrict__ dih,
    const float* __restrict__ degrees,
    float* __restrict__ out_aligned,   // N*45
    float* __restrict__ out_next,      // N*3
    float4* __restrict__ out_chi,      // N*72 float4
    int N)
{
    __shared__ float sDeg[ABLK * 4];
    __shared__ float sAT[ABLK][13];

    const int tid  = threadIdx.x;
    const int base = blockIdx.x * ABLK;
    const int res  = base + tid;

    // ---- coalesced staging of degrees ----
    {
        const size_t b4 = (size_t)base * 4;
        const int lim4 = N * 4 - (int)b4;
        #pragma unroll
        for (int k = 0; k < 4; ++k) {
            int idx = k * ABLK + tid;
            if (idx < lim4) sDeg[idx] = degrees[b4 + idx];
        }
    }
    __syncthreads();

    // NOTE: branch is uniform per-block (blockIdx), so inner __syncthreads is legal.
    if ((blockIdx.x & 1) == 0) {
        // store-stream first
        phase_chi_zero(out_chi, base, tid, N);
        __syncthreads();                       // order zero-pass vs active-pass
        phase_chi_active(sDeg, out_chi, base, tid, N);
        phase_kabsch_nerf(fixedp, mobilep, prev, bl, ban, dih,
                          out_next, sAT, res, tid, N);
        __syncthreads();
        phase_transform(coords, out_aligned, sAT, base, tid, N);
    } else {
        // ALU first
        phase_kabsch_nerf(fixedp, mobilep, prev, bl, ban, dih,
                          out_next, sAT, res, tid, N);
        __syncthreads();
        phase_transform(coords, out_aligned, sAT, base, tid, N);
        phase_chi_zero(out_chi, base, tid, N);
        __syncthreads();                       // order zero-pass vs active-pass
        phase_chi_active(sDeg, out_chi, base, tid, N);
    }
}

// ---------------------------------------------------------------------------
// Launch
// ---------------------------------------------------------------------------
extern "C" void kernel_launch(void* const* d_in, const int* in_sizes, int n_in,
                              void* d_out, int out_size)
{
    const float* fixedp  = (const float*)d_in[0];
    const float* mobilep = (const float*)d_in[1];
    const float* coords  = (const float*)d_in[2];
    const float* prev    = (const float*)d_in[3];
    const float* bl      = (const float*)d_in[4];
    const float* ban     = (const float*)d_in[5];
    const float* dih     = (const float*)d_in[6];
    const float* degrees = (const float*)d_in[7];

    const int N = in_sizes[4];  // bond_lengths is (N,1)

    float* out         = (float*)d_out;
    float* out_aligned = out;                       // N*45
    float* out_next    = out + (size_t)N * 45;      // N*3
    float* out_chi     = out + (size_t)N * 48;      // N*288 (16B aligned)

    fused_kernel<<<(N + ABLK - 1) / ABLK, ABLK>>>(
        fixedp, mobilep, coords, prev, bl, ban, dih, degrees,
        out_aligned, out_next, (float4*)out_chi, N);
}

// round 11
// speedup vs baseline: 1.4758x; 1.4758x over previous
#include <cuda_runtime.h>
#include <math.h>

// ---------------------------------------------------------------------------
// Helpers
// ---------------------------------------------------------------------------
__device__ __forceinline__ float det3f(float a0, float a1, float a2,
                                       float b0, float b1, float b2,
                                       float c0, float c1, float c2) {
    return a0 * (b1 * c2 - b2 * c1)
         - a1 * (b0 * c2 - b2 * c0)
         + a2 * (b0 * c1 - b1 * c0);
}

__device__ __forceinline__ void cross4f(const float a[4], const float b[4],
                                        const float c[4], float q[4]) {
    q[0] =  det3f(a[1], a[2], a[3], b[1], b[2], b[3], c[1], c[2], c[3]);
    q[1] = -det3f(a[0], a[2], a[3], b[0], b[2], b[3], c[0], c[2], c[3]);
    q[2] =  det3f(a[0], a[1], a[3], b[0], b[1], b[3], c[0], c[1], c[3]);
    q[3] = -det3f(a[0], a[1], a[2], b[0], b[1], b[2], c[0], c[1], c[2]);
}

// Best null-vector of (N - lam*I): try all four row-triples, keep max-norm.
__device__ __forceinline__ void null4(const float N0[4], const float N1[4],
                                      const float N2[4], const float N3[4],
                                      float lam, float q[4]) {
    float M0[4] = {N0[0] - lam, N0[1], N0[2], N0[3]};
    float M1[4] = {N1[0], N1[1] - lam, N1[2], N1[3]};
    float M2[4] = {N2[0], N2[1], N2[2] - lam, N2[3]};
    float M3[4] = {N3[0], N3[1], N3[2], N3[3] - lam};
    float cand[4];
    float best;

    cross4f(M1, M2, M3, cand);
    best = cand[0]*cand[0] + cand[1]*cand[1] + cand[2]*cand[2] + cand[3]*cand[3];
    q[0] = cand[0]; q[1] = cand[1]; q[2] = cand[2]; q[3] = cand[3];

    cross4f(M0, M2, M3, cand);
    {
        float n2 = cand[0]*cand[0] + cand[1]*cand[1] + cand[2]*cand[2] + cand[3]*cand[3];
        if (n2 > best) { best = n2; q[0]=cand[0]; q[1]=cand[1]; q[2]=cand[2]; q[3]=cand[3]; }
    }
    cross4f(M0, M1, M3, cand);
    {
        float n2 = cand[0]*cand[0] + cand[1]*cand[1] + cand[2]*cand[2] + cand[3]*cand[3];
        if (n2 > best) { best = n2; q[0]=cand[0]; q[1]=cand[1]; q[2]=cand[2]; q[3]=cand[3]; }
    }
    cross4f(M0, M1, M2, cand);
    {
        float n2 = cand[0]*cand[0] + cand[1]*cand[1] + cand[2]*cand[2] + cand[3]*cand[3];
        if (n2 > best) { best = n2; q[0]=cand[0]; q[1]=cand[1]; q[2]=cand[2]; q[3]=cand[3]; }
    }
}

// One Rayleigh-quotient refinement: normalize q, lam = q^T N q, re-extract.
__device__ __forceinline__ void rayleigh_refine(const float N0[4], const float N1[4],
                                                const float N2[4], const float N3[4],
                                                float q[4]) {
    float n2 = q[0]*q[0] + q[1]*q[1] + q[2]*q[2] + q[3]*q[3];
    if (n2 > 1e-30f) {
        float inv = rsqrtf(n2);
        float w = q[0]*inv, x = q[1]*inv, y = q[2]*inv, z = q[3]*inv;
        float t0 = N0[0]*w + N0[1]*x + N0[2]*y + N0[3]*z;
        float t1 = N1[0]*w + N1[1]*x + N1[2]*y + N1[3]*z;
        float t2 = N2[0]*w + N2[1]*x + N2[2]*y + N2[3]*z;
        float t3 = N3[0]*w + N3[1]*x + N3[2]*y + N3[3]*z;
        float lam = w*t0 + x*t1 + y*t2 + z*t3;
        null4(N0, N1, N2, N3, lam, q);
    }
}

#define ABLK 128

// ---------------------------------------------------------------------------
// Phase: Kabsch + NeRF (proven config: Newton 14 + 2x Rayleigh)
// ---------------------------------------------------------------------------
__device__ __forceinline__ void phase_kabsch_nerf(
    const float* __restrict__ fixedp, const float* __restrict__ mobilep,
    const float* __restrict__ prev, const float* __restrict__ bl,
    const float* __restrict__ ban, const float* __restrict__ dih,
    float* __restrict__ out_next, float (*sAT)[13], int res, int tid, int N)
{
    if (res >= N) return;

    {
        const float* fp = fixedp  + (size_t)res * 9;
        const float* mp = mobilep + (size_t)res * 9;
        float f0x = fp[0], f0y = fp[1], f0z = fp[2];
        float f1x = fp[3], f1y = fp[4], f1z = fp[5];
        float f2x = fp[6], f2y = fp[7], f2z = fp[8];
        float m0x = mp[0], m0y = mp[1], m0z = mp[2];
        float m1x = mp[3], m1y = mp[4], m1z = mp[5];
        float m2x = mp[6], m2y = mp[7], m2z = mp[8];

        const float third = 1.0f / 3.0f;
        float fcx = (f0x + f1x + f2x) * third;
        float fcy = (f0y + f1y + f2y) * third;
        float fcz = (f0z + f1z + f2z) * third;
        float mcx = (m0x + m1x + m2x) * third;
        float mcy = (m0y + m1y + m2y) * third;
        float mcz = (m0z + m1z + m2z) * third;

        float a0x = m0x - mcx, a0y = m0y - mcy, a0z = m0z - mcz;
        float a1x = m1x - mcx, a1y = m1y - mcy, a1z = m1z - mcz;
        float a2x = m2x - mcx, a2y = m2y - mcy, a2z = m2z - mcz;
        float b0x = f0x - fcx, b0y = f0y - fcy, b0z = f0z - fcz;
        float b1x = f1x - fcx, b1y = f1y - fcy, b1z = f1z - fcz;
        float b2x = f2x - fcx, b2y = f2y - fcy, b2z = f2z - fcz;

        float Sxx = a0x*b0x + a1x*b1x + a2x*b2x;
        float Sxy = a0x*b0y + a1x*b1y + a2x*b2y;
        float Sxz = a0x*b0z + a1x*b1z + a2x*b2z;
        float Syx = a0y*b0x + a1y*b1x + a2y*b2x;
        float Syy = a0y*b0y + a1y*b1y + a2y*b2y;
        float Syz = a0y*b0z + a1y*b1z + a2y*b2z;
        float Szx = a0z*b0x + a1z*b1x + a2z*b2x;
        float Szy = a0z*b0y + a1z*b1y + a2z*b2y;
        float Szz = a0z*b0z + a1z*b1z + a2z*b2z;

        float N0[4] = {Sxx + Syy + Szz, Syz - Szy, Szx - Sxz, Sxy - Syx};
        float N1[4] = {N0[1], Sxx - Syy - Szz, Sxy + Syx, Szx + Sxz};
        float N2[4] = {N0[2], N1[2], -Sxx + Syy - Szz, Syz + Szy};
        float N3[4] = {N0[3], N1[3], N2[3], -Sxx - Syy + Szz};

        float fro2 = Sxx*Sxx + Sxy*Sxy + Sxz*Sxz
                   + Syx*Syx + Syy*Syy + Syz*Syz
                   + Szx*Szx + Szy*Szy + Szz*Szz;
        float c2 = -2.0f * fro2;
        float c1 = -8.0f * det3f(Sxx, Sxy, Sxz, Syx, Syy, Syz, Szx, Szy, Szz);
        float cof[4];
        cross4f(N1, N2, N3, cof);
        float c0 = N0[0]*cof[0] + N0[1]*cof[1] + N0[2]*cof[2] + N0[3]*cof[3];

        // Newton from upper bound sqrt(-2 c2). 14 iterations: proven floor (R3).
        float lam = sqrtf(fmaxf(-2.0f * c2, 0.0f));
        #pragma unroll 1
        for (int it = 0; it < 14; ++it) {
            float l2 = lam * lam;
            float fv = l2 * l2 + c2 * l2 + c1 * lam + c0;
            float fd = 4.0f * l2 * lam + 2.0f * c2 * lam + c1;
            fd = (fabsf(fd) > 1e-12f) ? fd : 1e-12f;
            lam -= __fdividef(fv, fd);
        }

        float q[4];
        null4(N0, N1, N2, N3, lam, q);
        rayleigh_refine(N0, N1, N2, N3, q);
        rayleigh_refine(N0, N1, N2, N3, q);

        float n2 = q[0]*q[0] + q[1]*q[1] + q[2]*q[2] + q[3]*q[3];
        if (n2 < 1e-30f) { q[0] = 1.0f; q[1] = q[2] = q[3] = 0.0f; n2 = 1.0f; }
        float inv = rsqrtf(n2);
        float w = q[0]*inv, x = q[1]*inv, y = q[2]*inv, z = q[3]*inv;

        float A00 = 1.0f - 2.0f*(y*y + z*z);
        float A01 = 2.0f*(x*y - w*z);
        float A02 = 2.0f*(x*z + w*y);
        float A10 = 2.0f*(x*y + w*z);
        float A11 = 1.0f - 2.0f*(x*x + z*z);
        float A12 = 2.0f*(y*z - w*x);
        float A20 = 2.0f*(x*z - w*y);
        float A21 = 2.0f*(y*z + w*x);
        float A22 = 1.0f - 2.0f*(x*x + y*y);

        float* s = sAT[tid];
        s[0] = A00; s[1] = A01; s[2] = A02;
        s[3] = A10; s[4] = A11; s[5] = A12;
        s[6] = A20; s[7] = A21; s[8] = A22;
        s[9]  = fcx - (A00*mcx + A01*mcy + A02*mcz);
        s[10] = fcy - (A10*mcx + A11*mcy + A12*mcz);
        s[11] = fcz - (A20*mcx + A21*mcy + A22*mcz);
    }

    {
        const float* p = prev + (size_t)res * 9;
        float p0x = p[0], p0y = p[1], p0z = p[2];
        float p1x = p[3], p1y = p[4], p1z = p[5];
        float p2x = p[6], p2y = p[7], p2z = p[8];

        float bcx = p1x - p2x, bcy = p1y - p2y, bcz = p1z - p2z;
        float invn = 1.0f / (sqrtf(bcx*bcx + bcy*bcy + bcz*bcz) + 1e-6f);
        bcx *= invn; bcy *= invn; bcz *= invn;

        float ux = p1x - p0x, uy = p1y - p0y, uz = p1z - p0z;
        float bax = uy*bcz - uz*bcy;
        float bay = uz*bcx - ux*bcz;
        float baz = ux*bcy - uy*bcx;
        invn = 1.0f / (sqrtf(bax*bax + bay*bay + baz*baz) + 1e-6f);
        bax *= invn; bay *= invn; baz *= invn;

        float m1x = bay*bcz - baz*bcy;
        float m1y = baz*bcx - bax*bcz;
        float m1z = bax*bcy - bay*bcx;

        float L = bl[res], A = ban[res], D = dih[res];
        float sA = sinf(A), cA = cosf(A);
        float sD = sinf(D), cD = cosf(D);
        float d1 = L * cA;
        float d2 = L * sA * cD;
        float d3 = -L * sA * sD;

        float* o = out_next + (size_t)res * 3;
        o[0] = p2x + bcx*d1 + m1x*d2 + bax*d3;
        o[1] = p2y + bcy*d1 + m1y*d2 + bay*d3;
        o[2] = p2z + bcz*d1 + m1z*d2 + baz*d3;
    }
}

// ---------------------------------------------------------------------------
// Transform with float4 shared staging (full blocks; nres==ABLK path).
//  in : 12 coalesced LDG.128/thread -> sC
//  mid: thread tid processes residue tid in-place (lane stride 45 = 13 mod 32,
//       gcd(13,32)=1 -> conflict-free LDS/STS)
//  out: 12 coalesced STG.128/thread
// ---------------------------------------------------------------------------
__device__ __forceinline__ void phase_transform_staged(
    const float* __restrict__ coords, float* __restrict__ out_aligned,
    const float (*sAT)[13], float* __restrict__ sC, int base, int tid)
{
    const float4* c4 = (const float4*)(coords + (size_t)base * 45);
    float4* s4 = (float4*)sC;
    #pragma unroll
    for (int k = 0; k < 12; ++k) {
        int i = k * ABLK + tid;
        if (i < (ABLK * 45) / 4) s4[i] = __ldcs(&c4[i]);
    }
    __syncthreads();

    {
        float* rowc = sC + tid * 45;
        const float* s = sAT[tid];
        float A00 = s[0], A01 = s[1], A02 = s[2];
        float A10 = s[3], A11 = s[4], A12 = s[5];
        float A20 = s[6], A21 = s[7], A22 = s[8];
        float tx = s[9], ty = s[10], tz = s[11];
        #pragma unroll
        for (int at = 0; at < 15; ++at) {
            float px = rowc[at * 3 + 0];
            float py = rowc[at * 3 + 1];
            float pz = rowc[at * 3 + 2];
            rowc[at * 3 + 0] = A00*px + A01*py + A02*pz + tx;
            rowc[at * 3 + 1] = A10*px + A11*py + A12*pz + ty;
            rowc[at * 3 + 2] = A20*px + A21*py + A22*pz + tz;
        }
    }
    __syncthreads();

    float4* o4 = (float4*)(out_aligned + (size_t)base * 45);
    #pragma unroll
    for (int k = 0; k < 12; ++k) {
        int i = k * ABLK + tid;
        if (i < (ABLK * 45) / 4) __stcs(&o4[i], s4[i]);
    }
}

// Scalar fallback for partial tail blocks (not taken at N=400000).
__device__ __forceinline__ void phase_transform_scalar(
    const float* __restrict__ coords, float* __restrict__ out_aligned,
    const float (*sAT)[13], int base, int tid, int N)
{
    int nres = N - base;
    if (nres > ABLK) nres = ABLK;
    const int atomsTotal = nres * 15;
    #pragma unroll
    for (int k = 0; k < 15; ++k) {
        int a = k * ABLK + tid;
        if (a < atomsTotal) {
            int rl = a / 15;
            const float* cp = coords + (size_t)base * 45 + a * 3;
            float px = __ldcs(cp + 0);
            float py = __ldcs(cp + 1);
            float pz = __ldcs(cp + 2);
            const float* s = sAT[rl];
            float ox = s[0]*px + s[1]*py + s[2]*pz + s[9];
            float oy = s[3]*px + s[4]*py + s[5]*pz + s[10];
            float oz = s[6]*px + s[7]*py + s[8]*pz + s[11];
            float* op = out_aligned + (size_t)base * 45 + a * 3;
            __stcs(op + 0, ox);
            __stcs(op + 1, oy);
            __stcs(op + 2, oz);
        }
    }
}

// ---------------------------------------------------------------------------
// Chi RBF (R6 champion version: full 18 groups, min-based wrap, coalesced)
// ---------------------------------------------------------------------------
__device__ __forceinline__ void phase_chi(
    const float* __restrict__ sDeg, float4* __restrict__ out_chi,
    int base, int tid, int N)
{
    float4* chi = out_chi + (size_t)base * 72;
    int nres = N - base;
    if (nres > ABLK) nres = ABLK;
    const int groupsTotal = nres * 72;

    // incremental index split: v = rowl*18 + grp; step 128 = 7*18 + 2
    int v    = tid;
    int rowl = tid / 18;
    int grp  = tid - rowl * 18;
    #pragma unroll 1
    for (; v < groupsTotal; v += ABLK) {
        float deg = sDeg[rowl];
        float cbase = -180.0f + 20.0f * (float)grp;
        float r0, r1, r2, r3;
        {
            float ad = fabsf(deg - cbase);
            float dw = fminf(ad, 360.0f - ad);
            r0 = __expf(-0.08f * dw * dw);
        }
        {
            float ad = fabsf(deg - (cbase + 5.0f));
            float dw = fminf(ad, 360.0f - ad);
            r1 = __expf(-0.08f * dw * dw);
        }
        {
            float ad = fabsf(deg - (cbase + 10.0f));
            float dw = fminf(ad, 360.0f - ad);
            r2 = __expf(-0.08f * dw * dw);
        }
        {
            float ad = fabsf(deg - (cbase + 15.0f));
            float dw = fminf(ad, 360.0f - ad);
            r3 = __expf(-0.08f * dw * dw);
        }
        __stcs(&chi[v], make_float4(r0, r1, r2, r3));

        grp  += 2;
        rowl += 7;
        if (grp >= 18) { grp -= 18; ++rowl; }
    }
}

// ---------------------------------------------------------------------------
// Fused kernel with phase-parity scheduling (per-block uniform branches).
// ---------------------------------------------------------------------------
__global__ void __launch_bounds__(ABLK) fused_kernel(
    const float* __restrict__ fixedp,
    const float* __restrict__ mobilep,
    const float* __restrict__ coords,
    const float* __restrict__ prev,
    const float* __restrict__ bl,
    const float* __restrict__ ban,
    const float* __restrict__ dih,
    const float* __restrict__ degrees,
    float* __restrict__ out_aligned,   // N*45
    float* __restrict__ out_next,      // N*3
    float4* __restrict__ out_chi,      // N*72 float4
    int N)
{
    __shared__ float sDeg[ABLK * 4];
    __shared__ float sAT[ABLK][13];
    __shared__ float sC[ABLK * 45];    // float4-staged coords/output buffer

    const int tid  = threadIdx.x;
    const int base = blockIdx.x * ABLK;
    const int res  = base + tid;
    const bool fullBlock = (N - base) >= ABLK;

    // ---- coalesced staging of degrees ----
    {
        const size_t b4 = (size_t)base * 4;
        const int lim4 = N * 4 - (int)b4;
        #pragma unroll
        for (int k = 0; k < 4; ++k) {
            int idx = k * ABLK + tid;
            if (idx < lim4) sDeg[idx] = degrees[b4 + idx];
        }
    }
    __syncthreads();

    if ((blockIdx.x & 1) == 0) {
        // store-stream first
        phase_chi(sDeg, out_chi, base, tid, N);
        phase_kabsch_nerf(fixedp, mobilep, prev, bl, ban, dih,
                          out_next, sAT, res, tid, N);
        __syncthreads();
        if (fullBlock)
            phase_transform_staged(coords, out_aligned, sAT, sC, base, tid);
        else
            phase_transform_scalar(coords, out_aligned, sAT, base, tid, N);
    } else {
        // ALU first
        phase_kabsch_nerf(fixedp, mobilep, prev, bl, ban, dih,
                          out_next, sAT, res, tid, N);
        __syncthreads();
        if (fullBlock)
            phase_transform_staged(coords, out_aligned, sAT, sC, base, tid);
        else
            phase_transform_scalar(coords, out_aligned, sAT, base, tid, N);
        phase_chi(sDeg, out_chi, base, tid, N);
    }
}

// ---------------------------------------------------------------------------
// Launch
// ---------------------------------------------------------------------------
extern "C" void kernel_launch(void* const* d_in, const int* in_sizes, int n_in,
                              void* d_out, int out_size)
{
    const float* fixedp  = (const float*)d_in[0];
    const float* mobilep = (const float*)d_in[1];
    const float* coords  = (const float*)d_in[2];
    const float* prev    = (const float*)d_in[3];
    const float* bl      = (const float*)d_in[4];
    const float* ban     = (const float*)d_in[5];
    const float* dih     = (const float*)d_in[6];
    const float* degrees = (const float*)d_in[7];

    const int N = in_sizes[4];  // bond_lengths is (N,1)

    float* out         = (float*)d_out;
    float* out_aligned = out;                       // N*45
    float* out_next    = out + (size_t)N * 45;      // N*3
    float* out_chi     = out + (size_t)N * 48;      // N*288 (16B aligned)

    fused_kernel<<<(N + ABLK - 1) / ABLK, ABLK>>>(
        fixedp, mobilep, coords, prev, bl, ban, dih, degrees,
        out_aligned, out_next, (float4*)out_chi, N);
}

// round 12
// speedup vs baseline: 1.5291x; 1.0361x over previous
#include <cuda_runtime.h>
#include <math.h>

// ---------------------------------------------------------------------------
// Helpers
// ---------------------------------------------------------------------------
__device__ __forceinline__ float det3f(float a0, float a1, float a2,
                                       float b0, float b1, float b2,
                                       float c0, float c1, float c2) {
    return a0 * (b1 * c2 - b2 * c1)
         - a1 * (b0 * c2 - b2 * c0)
         + a2 * (b0 * c1 - b1 * c0);
}

__device__ __forceinline__ void cross4f(const float a[4], const float b[4],
                                        const float c[4], float q[4]) {
    q[0] =  det3f(a[1], a[2], a[3], b[1], b[2], b[3], c[1], c[2], c[3]);
    q[1] = -det3f(a[0], a[2], a[3], b[0], b[2], b[3], c[0], c[2], c[3]);
    q[2] =  det3f(a[0], a[1], a[3], b[0], b[1], b[3], c[0], c[1], c[3]);
    q[3] = -det3f(a[0], a[1], a[2], b[0], b[1], b[2], c[0], c[1], c[2]);
}

// Best null-vector of (N - lam*I): try all four row-triples, keep max-norm.
__device__ __forceinline__ void null4(const float N0[4], const float N1[4],
                                      const float N2[4], const float N3[4],
                                      float lam, float q[4]) {
    float M0[4] = {N0[0] - lam, N0[1], N0[2], N0[3]};
    float M1[4] = {N1[0], N1[1] - lam, N1[2], N1[3]};
    float M2[4] = {N2[0], N2[1], N2[2] - lam, N2[3]};
    float M3[4] = {N3[0], N3[1], N3[2], N3[3] - lam};
    float cand[4];
    float best;

    cross4f(M1, M2, M3, cand);
    best = cand[0]*cand[0] + cand[1]*cand[1] + cand[2]*cand[2] + cand[3]*cand[3];
    q[0] = cand[0]; q[1] = cand[1]; q[2] = cand[2]; q[3] = cand[3];

    cross4f(M0, M2, M3, cand);
    {
        float n2 = cand[0]*cand[0] + cand[1]*cand[1] + cand[2]*cand[2] + cand[3]*cand[3];
        if (n2 > best) { best = n2; q[0]=cand[0]; q[1]=cand[1]; q[2]=cand[2]; q[3]=cand[3]; }
    }
    cross4f(M0, M1, M3, cand);
    {
        float n2 = cand[0]*cand[0] + cand[1]*cand[1] + cand[2]*cand[2] + cand[3]*cand[3];
        if (n2 > best) { best = n2; q[0]=cand[0]; q[1]=cand[1]; q[2]=cand[2]; q[3]=cand[3]; }
    }
    cross4f(M0, M1, M2, cand);
    {
        float n2 = cand[0]*cand[0] + cand[1]*cand[1] + cand[2]*cand[2] + cand[3]*cand[3];
        if (n2 > best) { best = n2; q[0]=cand[0]; q[1]=cand[1]; q[2]=cand[2]; q[3]=cand[3]; }
    }
}

// One Rayleigh-quotient refinement: normalize q, lam = q^T N q, re-extract.
__device__ __forceinline__ void rayleigh_refine(const float N0[4], const float N1[4],
                                                const float N2[4], const float N3[4],
                                                float q[4]) {
    float n2 = q[0]*q[0] + q[1]*q[1] + q[2]*q[2] + q[3]*q[3];
    if (n2 > 1e-30f) {
        float inv = rsqrtf(n2);
        float w = q[0]*inv, x = q[1]*inv, y = q[2]*inv, z = q[3]*inv;
        float t0 = N0[0]*w + N0[1]*x + N0[2]*y + N0[3]*z;
        float t1 = N1[0]*w + N1[1]*x + N1[2]*y + N1[3]*z;
        float t2 = N2[0]*w + N2[1]*x + N2[2]*y + N2[3]*z;
        float t3 = N3[0]*w + N3[1]*x + N3[2]*y + N3[3]*z;
        float lam = w*t0 + x*t1 + y*t2 + z*t3;
        null4(N0, N1, N2, N3, lam, q);
    }
}

#define ABLK 128

// ---------------------------------------------------------------------------
// Phase: Kabsch + NeRF (proven config: Newton 14 + 2x Rayleigh)
// ---------------------------------------------------------------------------
__device__ __forceinline__ void phase_kabsch_nerf(
    const float* __restrict__ fixedp, const float* __restrict__ mobilep,
    const float* __restrict__ prev, const float* __restrict__ bl,
    const float* __restrict__ ban, const float* __restrict__ dih,
    float* __restrict__ out_next, float (*sAT)[13], int res, int tid, int N)
{
    if (res >= N) return;

    {
        const float* fp = fixedp  + (size_t)res * 9;
        const float* mp = mobilep + (size_t)res * 9;
        float f0x = fp[0], f0y = fp[1], f0z = fp[2];
        float f1x = fp[3], f1y = fp[4], f1z = fp[5];
        float f2x = fp[6], f2y = fp[7], f2z = fp[8];
        float m0x = mp[0], m0y = mp[1], m0z = mp[2];
        float m1x = mp[3], m1y = mp[4], m1z = mp[5];
        float m2x = mp[6], m2y = mp[7], m2z = mp[8];

        const float third = 1.0f / 3.0f;
        float fcx = (f0x + f1x + f2x) * third;
        float fcy = (f0y + f1y + f2y) * third;
        float fcz = (f0z + f1z + f2z) * third;
        float mcx = (m0x + m1x + m2x) * third;
        float mcy = (m0y + m1y + m2y) * third;
        float mcz = (m0z + m1z + m2z) * third;

        float a0x = m0x - mcx, a0y = m0y - mcy, a0z = m0z - mcz;
        float a1x = m1x - mcx, a1y = m1y - mcy, a1z = m1z - mcz;
        float a2x = m2x - mcx, a2y = m2y - mcy, a2z = m2z - mcz;
        float b0x = f0x - fcx, b0y = f0y - fcy, b0z = f0z - fcz;
        float b1x = f1x - fcx, b1y = f1y - fcy, b1z = f1z - fcz;
        float b2x = f2x - fcx, b2y = f2y - fcy, b2z = f2z - fcz;

        float Sxx = a0x*b0x + a1x*b1x + a2x*b2x;
        float Sxy = a0x*b0y + a1x*b1y + a2x*b2y;
        float Sxz = a0x*b0z + a1x*b1z + a2x*b2z;
        float Syx = a0y*b0x + a1y*b1x + a2y*b2x;
        float Syy = a0y*b0y + a1y*b1y + a2y*b2y;
        float Syz = a0y*b0z + a1y*b1z + a2y*b2z;
        float Szx = a0z*b0x + a1z*b1x + a2z*b2x;
        float Szy = a0z*b0y + a1z*b1y + a2z*b2y;
        float Szz = a0z*b0z + a1z*b1z + a2z*b2z;

        float N0[4] = {Sxx + Syy + Szz, Syz - Szy, Szx - Sxz, Sxy - Syx};
        float N1[4] = {N0[1], Sxx - Syy - Szz, Sxy + Syx, Szx + Sxz};
        float N2[4] = {N0[2], N1[2], -Sxx + Syy - Szz, Syz + Szy};
        float N3[4] = {N0[3], N1[3], N2[3], -Sxx - Syy + Szz};

        float fro2 = Sxx*Sxx + Sxy*Sxy + Sxz*Sxz
                   + Syx*Syx + Syy*Syy + Syz*Syz
                   + Szx*Szx + Szy*Szy + Szz*Szz;
        float c2 = -2.0f * fro2;
        float c1 = -8.0f * det3f(Sxx, Sxy, Sxz, Syx, Syy, Syz, Szx, Szy, Szz);
        float cof[4];
        cross4f(N1, N2, N3, cof);
        float c0 = N0[0]*cof[0] + N0[1]*cof[1] + N0[2]*cof[2] + N0[3]*cof[3];

        // Newton from upper bound sqrt(-2 c2). 14 iterations: proven floor (R3).
        float lam = sqrtf(fmaxf(-2.0f * c2, 0.0f));
        #pragma unroll 1
        for (int it = 0; it < 14; ++it) {
            float l2 = lam * lam;
            float fv = l2 * l2 + c2 * l2 + c1 * lam + c0;
            float fd = 4.0f * l2 * lam + 2.0f * c2 * lam + c1;
            fd = (fabsf(fd) > 1e-12f) ? fd : 1e-12f;
            lam -= __fdividef(fv, fd);
        }

        float q[4];
        null4(N0, N1, N2, N3, lam, q);
        rayleigh_refine(N0, N1, N2, N3, q);
        rayleigh_refine(N0, N1, N2, N3, q);

        float n2 = q[0]*q[0] + q[1]*q[1] + q[2]*q[2] + q[3]*q[3];
        if (n2 < 1e-30f) { q[0] = 1.0f; q[1] = q[2] = q[3] = 0.0f; n2 = 1.0f; }
        float inv = rsqrtf(n2);
        float w = q[0]*inv, x = q[1]*inv, y = q[2]*inv, z = q[3]*inv;

        float A00 = 1.0f - 2.0f*(y*y + z*z);
        float A01 = 2.0f*(x*y - w*z);
        float A02 = 2.0f*(x*z + w*y);
        float A10 = 2.0f*(x*y + w*z);
        float A11 = 1.0f - 2.0f*(x*x + z*z);
        float A12 = 2.0f*(y*z - w*x);
        float A20 = 2.0f*(x*z - w*y);
        float A21 = 2.0f*(y*z + w*x);
        float A22 = 1.0f - 2.0f*(x*x + y*y);

        float* s = sAT[tid];
        s[0] = A00; s[1] = A01; s[2] = A02;
        s[3] = A10; s[4] = A11; s[5] = A12;
        s[6] = A20; s[7] = A21; s[8] = A22;
        s[9]  = fcx - (A00*mcx + A01*mcy + A02*mcz);
        s[10] = fcy - (A10*mcx + A11*mcy + A12*mcz);
        s[11] = fcz - (A20*mcx + A21*mcy + A22*mcz);
    }

    {
        const float* p = prev + (size_t)res * 9;
        float p0x = p[0], p0y = p[1], p0z = p[2];
        float p1x = p[3], p1y = p[4], p1z = p[5];
        float p2x = p[6], p2y = p[7], p2z = p[8];

        float bcx = p1x - p2x, bcy = p1y - p2y, bcz = p1z - p2z;
        float invn = 1.0f / (sqrtf(bcx*bcx + bcy*bcy + bcz*bcz) + 1e-6f);
        bcx *= invn; bcy *= invn; bcz *= invn;

        float ux = p1x - p0x, uy = p1y - p0y, uz = p1z - p0z;
        float bax = uy*bcz - uz*bcy;
        float bay = uz*bcx - ux*bcz;
        float baz = ux*bcy - uy*bcx;
        invn = 1.0f / (sqrtf(bax*bax + bay*bay + baz*baz) + 1e-6f);
        bax *= invn; bay *= invn; baz *= invn;

        float m1x = bay*bcz - baz*bcy;
        float m1y = baz*bcx - bax*bcz;
        float m1z = bax*bcy - bay*bcx;

        float L = bl[res], A = ban[res], D = dih[res];
        float sA = sinf(A), cA = cosf(A);
        float sD = sinf(D), cD = cosf(D);
        float d1 = L * cA;
        float d2 = L * sA * cD;
        float d3 = -L * sA * sD;

        float* o = out_next + (size_t)res * 3;
        o[0] = p2x + bcx*d1 + m1x*d2 + bax*d3;
        o[1] = p2y + bcy*d1 + m1y*d2 + bay*d3;
        o[2] = p2z + bcz*d1 + m1z*d2 + baz*d3;
    }
}

// ---------------------------------------------------------------------------
// Transform with float4 shared staging, in TWO 64-residue chunks to halve
// the shared buffer (occupancy). Per chunk:
//  in : 6 coalesced LDG.128/thread -> sC (720 float4)
//  mid: rl = tid & 63, half = tid >> 6; half 0 -> atoms 0..7, half 1 -> 8..14.
//       Warp lanes have rl consecutive -> 45*rl mod 32 distinct -> no conflicts.
//  out: 6 coalesced STG.128/thread
// ---------------------------------------------------------------------------
__device__ __forceinline__ void phase_transform_staged(
    const float* __restrict__ coords, float* __restrict__ out_aligned,
    const float (*sAT)[13], float* __restrict__ sC, int base, int tid)
{
    #pragma unroll 1
    for (int chunk = 0; chunk < 2; ++chunk) {
        const int rbase = chunk * 64;               // residue offset in block
        const float4* c4 = (const float4*)(coords + ((size_t)base + rbase) * 45);
        float4* s4 = (float4*)sC;
        // stage 64*45 = 2880 floats = 720 float4
        #pragma unroll
        for (int k = 0; k < 6; ++k) {
            int i = k * ABLK + tid;
            if (i < 720) s4[i] = __ldcs(&c4[i]);
        }
        __syncthreads();

        {
            const int rl   = tid & 63;
            const int half = tid >> 6;
            float* rowc = sC + rl * 45 + half * 24;
            const float* s = sAT[rbase + rl];
            float A00 = s[0], A01 = s[1], A02 = s[2];
            float A10 = s[3], A11 = s[4], A12 = s[5];
            float A20 = s[6], A21 = s[7], A22 = s[8];
            float tx = s[9], ty = s[10], tz = s[11];
            const int nat = half ? 7 : 8;
            #pragma unroll
            for (int at = 0; at < 8; ++at) {
                if (at < nat) {
                    float px = rowc[at * 3 + 0];
                    float py = rowc[at * 3 + 1];
                    float pz = rowc[at * 3 + 2];
                    rowc[at * 3 + 0] = A00*px + A01*py + A02*pz + tx;
                    rowc[at * 3 + 1] = A10*px + A11*py + A12*pz + ty;
                    rowc[at * 3 + 2] = A20*px + A21*py + A22*pz + tz;
                }
            }
        }
        __syncthreads();

        float4* o4 = (float4*)(out_aligned + ((size_t)base + rbase) * 45);
        #pragma unroll
        for (int k = 0; k < 6; ++k) {
            int i = k * ABLK + tid;
            if (i < 720) __stcs(&o4[i], s4[i]);
        }
        if (chunk == 0) __syncthreads();   // protect sC reuse
    }
}

// Scalar fallback for partial tail blocks (not taken at N=400000).
__device__ __forceinline__ void phase_transform_scalar(
    const float* __restrict__ coords, float* __restrict__ out_aligned,
    const float (*sAT)[13], int base, int tid, int N)
{
    int nres = N - base;
    if (nres > ABLK) nres = ABLK;
    const int atomsTotal = nres * 15;
    #pragma unroll
    for (int k = 0; k < 15; ++k) {
        int a = k * ABLK + tid;
        if (a < atomsTotal) {
            int rl = a / 15;
            const float* cp = coords + (size_t)base * 45 + a * 3;
            float px = __ldcs(cp + 0);
            float py = __ldcs(cp + 1);
            float pz = __ldcs(cp + 2);
            const float* s = sAT[rl];
            float ox = s[0]*px + s[1]*py + s[2]*pz + s[9];
            float oy = s[3]*px + s[4]*py + s[5]*pz + s[10];
            float oz = s[6]*px + s[7]*py + s[8]*pz + s[11];
            float* op = out_aligned + (size_t)base * 45 + a * 3;
            __stcs(op + 0, ox);
            __stcs(op + 1, oy);
            __stcs(op + 2, oz);
        }
    }
}

// ---------------------------------------------------------------------------
// Chi RBF (R6 proven version: full 18 groups, min-based wrap, coalesced)
// ---------------------------------------------------------------------------
__device__ __forceinline__ void phase_chi(
    const float* __restrict__ sDeg, float4* __restrict__ out_chi,
    int base, int tid, int N)
{
    float4* chi = out_chi + (size_t)base * 72;
    int nres = N - base;
    if (nres > ABLK) nres = ABLK;
    const int groupsTotal = nres * 72;

    // incremental index split: v = rowl*18 + grp; step 128 = 7*18 + 2
    int v    = tid;
    int rowl = tid / 18;
    int grp  = tid - rowl * 18;
    #pragma unroll 1
    for (; v < groupsTotal; v += ABLK) {
        float deg = sDeg[rowl];
        float cbase = -180.0f + 20.0f * (float)grp;
        float r0, r1, r2, r3;
        {
            float ad = fabsf(deg - cbase);
            float dw = fminf(ad, 360.0f - ad);
            r0 = __expf(-0.08f * dw * dw);
        }
        {
            float ad = fabsf(deg - (cbase + 5.0f));
            float dw = fminf(ad, 360.0f - ad);
            r1 = __expf(-0.08f * dw * dw);
        }
        {
            float ad = fabsf(deg - (cbase + 10.0f));
            float dw = fminf(ad, 360.0f - ad);
            r2 = __expf(-0.08f * dw * dw);
        }
        {
            float ad = fabsf(deg - (cbase + 15.0f));
            float dw = fminf(ad, 360.0f - ad);
            r3 = __expf(-0.08f * dw * dw);
        }
        __stcs(&chi[v], make_float4(r0, r1, r2, r3));

        grp  += 2;
        rowl += 7;
        if (grp >= 18) { grp -= 18; ++rowl; }
    }
}

// ---------------------------------------------------------------------------
// Fused kernel with phase-parity scheduling (per-block uniform branches).
// __launch_bounds__(128, 8): cap regs at 64 -> 8 blocks/SM (50% occupancy).
// ---------------------------------------------------------------------------
__global__ void __launch_bounds__(ABLK, 8) fused_kernel(
    const float* __restrict__ fixedp,
    const float* __restrict__ mobilep,
    const float* __restrict__ coords,
    const float* __restrict__ prev,
    const float* __restrict__ bl,
    const float* __restrict__ ban,
    const float* __restrict__ dih,
    const float* __restrict__ degrees,
    float* __restrict__ out_aligned,   // N*45
    float* __restrict__ out_next,      // N*3
    float4* __restrict__ out_chi,      // N*72 float4
    int N)
{
    __shared__ float sDeg[ABLK * 4];
    __shared__ float sAT[ABLK][13];
    __shared__ float sC[64 * 45];      // half-block float4 staging buffer

    const int tid  = threadIdx.x;
    const int base = blockIdx.x * ABLK;
    const int res  = base + tid;
    const bool fullBlock = (N - base) >= ABLK;

    // ---- coalesced staging of degrees ----
    {
        const size_t b4 = (size_t)base * 4;
        const int lim4 = N * 4 - (int)b4;
        #pragma unroll
        for (int k = 0; k < 4; ++k) {
            int idx = k * ABLK + tid;
            if (idx < lim4) sDeg[idx] = degrees[b4 + idx];
        }
    }
    __syncthreads();

    if ((blockIdx.x & 1) == 0) {
        // store-stream first
        phase_chi(sDeg, out_chi, base, tid, N);
        phase_kabsch_nerf(fixedp, mobilep, prev, bl, ban, dih,
                          out_next, sAT, res, tid, N);
        __syncthreads();
        if (fullBlock)
            phase_transform_staged(coords, out_aligned, sAT, sC, base, tid);
        else
            phase_transform_scalar(coords, out_aligned, sAT, base, tid, N);
    } else {
        // ALU first
        phase_kabsch_nerf(fixedp, mobilep, prev, bl, ban, dih,
                          out_next, sAT, res, tid, N);
        __syncthreads();
        if (fullBlock)
            phase_transform_staged(coords, out_aligned, sAT, sC, base, tid);
        else
            phase_transform_scalar(coords, out_aligned, sAT, base, tid, N);
        phase_chi(sDeg, out_chi, base, tid, N);
    }
}

// ---------------------------------------------------------------------------
// Launch
// ---------------------------------------------------------------------------
extern "C" void kernel_launch(void* const* d_in, const int* in_sizes, int n_in,
                              void* d_out, int out_size)
{
    const float* fixedp  = (const float*)d_in[0];
    const float* mobilep = (const float*)d_in[1];
    const float* coords  = (const float*)d_in[2];
    const float* prev    = (const float*)d_in[3];
    const float* bl      = (const float*)d_in[4];
    const float* ban     = (const float*)d_in[5];
    const float* dih     = (const float*)d_in[6];
    const float* degrees = (const float*)d_in[7];

    const int N = in_sizes[4];  // bond_lengths is (N,1)

    float* out         = (float*)d_out;
    float* out_aligned = out;                       // N*45
    float* out_next    = out + (size_t)N * 45;      // N*3
    float* out_chi     = out + (size_t)N * 48;      // N*288 (16B aligned)

    fused_kernel<<<(N + ABLK - 1) / ABLK, ABLK>>>(
        fixedp, mobilep, coords, prev, bl, ban, dih, degrees,
        out_aligned, out_next, (float4*)out_chi, N);
}

// round 13
// speedup vs baseline: 1.5764x; 1.0309x over previous
#include <cuda_runtime.h>
#include <math.h>

// ---------------------------------------------------------------------------
// Helpers
// ---------------------------------------------------------------------------
__device__ __forceinline__ float det3f(float a0, float a1, float a2,
                                       float b0, float b1, float b2,
                                       float c0, float c1, float c2) {
    return a0 * (b1 * c2 - b2 * c1)
         - a1 * (b0 * c2 - b2 * c0)
         + a2 * (b0 * c1 - b1 * c0);
}

__device__ __forceinline__ void cross4f(const float a[4], const float b[4],
                                        const float c[4], float q[4]) {
    q[0] =  det3f(a[1], a[2], a[3], b[1], b[2], b[3], c[1], c[2], c[3]);
    q[1] = -det3f(a[0], a[2], a[3], b[0], b[2], b[3], c[0], c[2], c[3]);
    q[2] =  det3f(a[0], a[1], a[3], b[0], b[1], b[3], c[0], c[1], c[3]);
    q[3] = -det3f(a[0], a[1], a[2], b[0], b[1], b[2], c[0], c[1], c[2]);
}

// Best null-vector of (N - lam*I): try all four row-triples, keep max-norm.
__device__ __forceinline__ void null4(const float N0[4], const float N1[4],
                                      const float N2[4], const float N3[4],
                                      float lam, float q[4]) {
    float M0[4] = {N0[0] - lam, N0[1], N0[2], N0[3]};
    float M1[4] = {N1[0], N1[1] - lam, N1[2], N1[3]};
    float M2[4] = {N2[0], N2[1], N2[2] - lam, N2[3]};
    float M3[4] = {N3[0], N3[1], N3[2], N3[3] - lam};
    float cand[4];
    float best;

    cross4f(M1, M2, M3, cand);
    best = cand[0]*cand[0] + cand[1]*cand[1] + cand[2]*cand[2] + cand[3]*cand[3];
    q[0] = cand[0]; q[1] = cand[1]; q[2] = cand[2]; q[3] = cand[3];

    cross4f(M0, M2, M3, cand);
    {
        float n2 = cand[0]*cand[0] + cand[1]*cand[1] + cand[2]*cand[2] + cand[3]*cand[3];
        if (n2 > best) { best = n2; q[0]=cand[0]; q[1]=cand[1]; q[2]=cand[2]; q[3]=cand[3]; }
    }
    cross4f(M0, M1, M3, cand);
    {
        float n2 = cand[0]*cand[0] + cand[1]*cand[1] + cand[2]*cand[2] + cand[3]*cand[3];
        if (n2 > best) { best = n2; q[0]=cand[0]; q[1]=cand[1]; q[2]=cand[2]; q[3]=cand[3]; }
    }
    cross4f(M0, M1, M2, cand);
    {
        float n2 = cand[0]*cand[0] + cand[1]*cand[1] + cand[2]*cand[2] + cand[3]*cand[3];
        if (n2 > best) { best = n2; q[0]=cand[0]; q[1]=cand[1]; q[2]=cand[2]; q[3]=cand[3]; }
    }
}

// One Rayleigh-quotient refinement: normalize q, lam = q^T N q, re-extract.
__device__ __forceinline__ void rayleigh_refine(const float N0[4], const float N1[4],
                                                const float N2[4], const float N3[4],
                                                float q[4]) {
    float n2 = q[0]*q[0] + q[1]*q[1] + q[2]*q[2] + q[3]*q[3];
    if (n2 > 1e-30f) {
        float inv = rsqrtf(n2);
        float w = q[0]*inv, x = q[1]*inv, y = q[2]*inv, z = q[3]*inv;
        float t0 = N0[0]*w + N0[1]*x + N0[2]*y + N0[3]*z;
        float t1 = N1[0]*w + N1[1]*x + N1[2]*y + N1[3]*z;
        float t2 = N2[0]*w + N2[1]*x + N2[2]*y + N2[3]*z;
        float t3 = N3[0]*w + N3[1]*x + N3[2]*y + N3[3]*z;
        float lam = w*t0 + x*t1 + y*t2 + z*t3;
        null4(N0, N1, N2, N3, lam, q);
    }
}

#define ABLK 128

// ---------------------------------------------------------------------------
// Phase: Kabsch + NeRF (proven config: Newton 14 + 2x Rayleigh)
// ---------------------------------------------------------------------------
__device__ __forceinline__ void phase_kabsch_nerf(
    const float* __restrict__ fixedp, const float* __restrict__ mobilep,
    const float* __restrict__ prev, const float* __restrict__ bl,
    const float* __restrict__ ban, const float* __restrict__ dih,
    float* __restrict__ out_next, float (*sAT)[13], int res, int tid, int N)
{
    if (res >= N) return;

    {
        const float* fp = fixedp  + (size_t)res * 9;
        const float* mp = mobilep + (size_t)res * 9;
        float f0x = fp[0], f0y = fp[1], f0z = fp[2];
        float f1x = fp[3], f1y = fp[4], f1z = fp[5];
        float f2x = fp[6], f2y = fp[7], f2z = fp[8];
        float m0x = mp[0], m0y = mp[1], m0z = mp[2];
        float m1x = mp[3], m1y = mp[4], m1z = mp[5];
        float m2x = mp[6], m2y = mp[7], m2z = mp[8];

        const float third = 1.0f / 3.0f;
        float fcx = (f0x + f1x + f2x) * third;
        float fcy = (f0y + f1y + f2y) * third;
        float fcz = (f0z + f1z + f2z) * third;
        float mcx = (m0x + m1x + m2x) * third;
        float mcy = (m0y + m1y + m2y) * third;
        float mcz = (m0z + m1z + m2z) * third;

        float a0x = m0x - mcx, a0y = m0y - mcy, a0z = m0z - mcz;
        float a1x = m1x - mcx, a1y = m1y - mcy, a1z = m1z - mcz;
        float a2x = m2x - mcx, a2y = m2y - mcy, a2z = m2z - mcz;
        float b0x = f0x - fcx, b0y = f0y - fcy, b0z = f0z - fcz;
        float b1x = f1x - fcx, b1y = f1y - fcy, b1z = f1z - fcz;
        float b2x = f2x - fcx, b2y = f2y - fcy, b2z = f2z - fcz;

        float Sxx = a0x*b0x + a1x*b1x + a2x*b2x;
        float Sxy = a0x*b0y + a1x*b1y + a2x*b2y;
        float Sxz = a0x*b0z + a1x*b1z + a2x*b2z;
        float Syx = a0y*b0x + a1y*b1x + a2y*b2x;
        float Syy = a0y*b0y + a1y*b1y + a2y*b2y;
        float Syz = a0y*b0z + a1y*b1z + a2y*b2z;
        float Szx = a0z*b0x + a1z*b1x + a2z*b2x;
        float Szy = a0z*b0y + a1z*b1y + a2z*b2y;
        float Szz = a0z*b0z + a1z*b1z + a2z*b2z;

        float N0[4] = {Sxx + Syy + Szz, Syz - Szy, Szx - Sxz, Sxy - Syx};
        float N1[4] = {N0[1], Sxx - Syy - Szz, Sxy + Syx, Szx + Sxz};
        float N2[4] = {N0[2], N1[2], -Sxx + Syy - Szz, Syz + Szy};
        float N3[4] = {N0[3], N1[3], N2[3], -Sxx - Syy + Szz};

        float fro2 = Sxx*Sxx + Sxy*Sxy + Sxz*Sxz
                   + Syx*Syx + Syy*Syy + Syz*Syz
                   + Szx*Szx + Szy*Szy + Szz*Szz;
        float c2 = -2.0f * fro2;
        float c1 = -8.0f * det3f(Sxx, Sxy, Sxz, Syx, Syy, Syz, Szx, Szy, Szz);
        float cof[4];
        cross4f(N1, N2, N3, cof);
        float c0 = N0[0]*cof[0] + N0[1]*cof[1] + N0[2]*cof[2] + N0[3]*cof[3];

        // Newton from upper bound sqrt(-2 c2). 14 iterations: proven floor (R3).
        float lam = sqrtf(fmaxf(-2.0f * c2, 0.0f));
        #pragma unroll 1
        for (int it = 0; it < 14; ++it) {
            float l2 = lam * lam;
            float fv = l2 * l2 + c2 * l2 + c1 * lam + c0;
            float fd = 4.0f * l2 * lam + 2.0f * c2 * lam + c1;
            fd = (fabsf(fd) > 1e-12f) ? fd : 1e-12f;
            lam -= __fdividef(fv, fd);
        }

        float q[4];
        null4(N0, N1, N2, N3, lam, q);
        rayleigh_refine(N0, N1, N2, N3, q);
        rayleigh_refine(N0, N1, N2, N3, q);

        float n2 = q[0]*q[0] + q[1]*q[1] + q[2]*q[2] + q[3]*q[3];
        if (n2 < 1e-30f) { q[0] = 1.0f; q[1] = q[2] = q[3] = 0.0f; n2 = 1.0f; }
        float inv = rsqrtf(n2);
        float w = q[0]*inv, x = q[1]*inv, y = q[2]*inv, z = q[3]*inv;

        float A00 = 1.0f - 2.0f*(y*y + z*z);
        float A01 = 2.0f*(x*y - w*z);
        float A02 = 2.0f*(x*z + w*y);
        float A10 = 2.0f*(x*y + w*z);
        float A11 = 1.0f - 2.0f*(x*x + z*z);
        float A12 = 2.0f*(y*z - w*x);
        float A20 = 2.0f*(x*z - w*y);
        float A21 = 2.0f*(y*z + w*x);
        float A22 = 1.0f - 2.0f*(x*x + y*y);

        float* s = sAT[tid];
        s[0] = A00; s[1] = A01; s[2] = A02;
        s[3] = A10; s[4] = A11; s[5] = A12;
        s[6] = A20; s[7] = A21; s[8] = A22;
        s[9]  = fcx - (A00*mcx + A01*mcy + A02*mcz);
        s[10] = fcy - (A10*mcx + A11*mcy + A12*mcz);
        s[11] = fcz - (A20*mcx + A21*mcy + A22*mcz);
    }

    {
        const float* p = prev + (size_t)res * 9;
        float p0x = p[0], p0y = p[1], p0z = p[2];
        float p1x = p[3], p1y = p[4], p1z = p[5];
        float p2x = p[6], p2y = p[7], p2z = p[8];

        float bcx = p1x - p2x, bcy = p1y - p2y, bcz = p1z - p2z;
        float invn = 1.0f / (sqrtf(bcx*bcx + bcy*bcy + bcz*bcz) + 1e-6f);
        bcx *= invn; bcy *= invn; bcz *= invn;

        float ux = p1x - p0x, uy = p1y - p0y, uz = p1z - p0z;
        float bax = uy*bcz - uz*bcy;
        float bay = uz*bcx - ux*bcz;
        float baz = ux*bcy - uy*bcx;
        invn = 1.0f / (sqrtf(bax*bax + bay*bay + baz*baz) + 1e-6f);
        bax *= invn; bay *= invn; baz *= invn;

        float m1x = bay*bcz - baz*bcy;
        float m1y = baz*bcx - bax*bcz;
        float m1z = bax*bcy - bay*bcx;

        float L = bl[res], A = ban[res], D = dih[res];
        float sA = sinf(A), cA = cosf(A);
        float sD = sinf(D), cD = cosf(D);
        float d1 = L * cA;
        float d2 = L * sA * cD;
        float d3 = -L * sA * sD;

        float* o = out_next + (size_t)res * 3;
        o[0] = p2x + bcx*d1 + m1x*d2 + bax*d3;
        o[1] = p2y + bcy*d1 + m1y*d2 + bay*d3;
        o[2] = p2z + bcz*d1 + m1z*d2 + baz*d3;
    }
}

// ---------------------------------------------------------------------------
// Transform with float4 shared staging, in TWO 64-residue chunks (R12 WIN).
// ---------------------------------------------------------------------------
__device__ __forceinline__ void phase_transform_staged(
    const float* __restrict__ coords, float* __restrict__ out_aligned,
    const float (*sAT)[13], float* __restrict__ sC, int base, int tid)
{
    #pragma unroll 1
    for (int chunk = 0; chunk < 2; ++chunk) {
        const int rbase = chunk * 64;
        const float4* c4 = (const float4*)(coords + ((size_t)base + rbase) * 45);
        float4* s4 = (float4*)sC;
        #pragma unroll
        for (int k = 0; k < 6; ++k) {
            int i = k * ABLK + tid;
            if (i < 720) s4[i] = __ldcs(&c4[i]);
        }
        __syncthreads();

        {
            const int rl   = tid & 63;
            const int half = tid >> 6;
            float* rowc = sC + rl * 45 + half * 24;
            const float* s = sAT[rbase + rl];
            float A00 = s[0], A01 = s[1], A02 = s[2];
            float A10 = s[3], A11 = s[4], A12 = s[5];
            float A20 = s[6], A21 = s[7], A22 = s[8];
            float tx = s[9], ty = s[10], tz = s[11];
            const int nat = half ? 7 : 8;
            #pragma unroll
            for (int at = 0; at < 8; ++at) {
                if (at < nat) {
                    float px = rowc[at * 3 + 0];
                    float py = rowc[at * 3 + 1];
                    float pz = rowc[at * 3 + 2];
                    rowc[at * 3 + 0] = A00*px + A01*py + A02*pz + tx;
                    rowc[at * 3 + 1] = A10*px + A11*py + A12*pz + ty;
                    rowc[at * 3 + 2] = A20*px + A21*py + A22*pz + tz;
                }
            }
        }
        __syncthreads();

        float4* o4 = (float4*)(out_aligned + ((size_t)base + rbase) * 45);
        #pragma unroll
        for (int k = 0; k < 6; ++k) {
            int i = k * ABLK + tid;
            if (i < 720) __stcs(&o4[i], s4[i]);
        }
        if (chunk == 0) __syncthreads();
    }
}

// Scalar fallback for partial tail blocks (not taken at N=400000).
__device__ __forceinline__ void phase_transform_scalar(
    const float* __restrict__ coords, float* __restrict__ out_aligned,
    const float (*sAT)[13], int base, int tid, int N)
{
    int nres = N - base;
    if (nres > ABLK) nres = ABLK;
    const int atomsTotal = nres * 15;
    #pragma unroll
    for (int k = 0; k < 15; ++k) {
        int a = k * ABLK + tid;
        if (a < atomsTotal) {
            int rl = a / 15;
            const float* cp = coords + (size_t)base * 45 + a * 3;
            float px = __ldcs(cp + 0);
            float py = __ldcs(cp + 1);
            float pz = __ldcs(cp + 2);
            const float* s = sAT[rl];
            float ox = s[0]*px + s[1]*py + s[2]*pz + s[9];
            float oy = s[3]*px + s[4]*py + s[5]*pz + s[10];
            float oz = s[6]*px + s[7]*py + s[8]*pz + s[11];
            float* op = out_aligned + (size_t)base * 45 + a * 3;
            __stcs(op + 0, ox);
            __stcs(op + 1, oy);
            __stcs(op + 2, oz);
        }
    }
}

// ---------------------------------------------------------------------------
// Chi RBF, windowed-into-shared (fixes R10's scattered-global-store failure):
// Only bins kc-7..kc+8 (16) can be nonzero in fp32 (others underflow exp to
// exactly 0, matching the fp32 reference). Per 32-row chunk:
//   1) all threads zero the 32x72 shared buffer (float4)
//   2) 4 threads/row compute 4 bins each of the 16-bin window (exact R6
//      formula: center = -180 + 5*bin, min-wrap, __expf) into shared
//   3) all threads copy out 576 float4 perfectly coalesced
// Global store pattern identical to the proven R6/R12 one.
// ---------------------------------------------------------------------------
__device__ __forceinline__ void phase_chi_windowed(
    const float* __restrict__ sDeg, float* __restrict__ sBuf,
    float4* __restrict__ out_chi, int base, int tid)
{
    float4* chi = out_chi + (size_t)base * 72;   // 72 float4 per residue
    float4* b4 = (float4*)sBuf;
    const int rloc = tid >> 2;   // 0..31
    const int sub  = tid & 3;    // 0..3

    #pragma unroll 1
    for (int c = 0; c < 16; ++c) {
        // 1) zero 32*72 floats = 576 float4
        #pragma unroll
        for (int k = 0; k < 5; ++k) {
            int i = k * ABLK + tid;
            if (i < 576) b4[i] = make_float4(0.0f, 0.0f, 0.0f, 0.0f);
        }
        __syncthreads();

        // 2) compute the 16-bin window for this thread's row
        {
            int row = c * 32 + rloc;             // 0..511
            float deg = sDeg[row];
            // nearest bin: kc = floor((deg+182.5)/5) in [0,72]
            int kc = (int)floorf((deg + 182.5f) * 0.2f);
            int w = kc + 65;                     // kc - 7 + 72 in [65,137]
            if (w >= 72) w -= 72;                // [0,71]
            float* rowp = sBuf + rloc * 72;
            #pragma unroll
            for (int i = 0; i < 4; ++i) {
                int b = w + sub * 4 + i;         // <= 71 + 15 = 86
                if (b >= 72) b -= 72;
                float cb = -180.0f + 5.0f * (float)b;
                float ad = fabsf(deg - cb);
                float dw = fminf(ad, 360.0f - ad);
                rowp[b] = __expf(-0.08f * dw * dw);
            }
        }
        __syncthreads();

        // 3) coalesced copy-out
        float4* o4 = chi + (size_t)c * 576;
        #pragma unroll
        for (int k = 0; k < 5; ++k) {
            int i = k * ABLK + tid;
            if (i < 576) __stcs(&o4[i], b4[i]);
        }
        __syncthreads();
    }
}

// R6 full fallback for partial tail blocks (not taken at N=400000).
__device__ __forceinline__ void phase_chi_scalar(
    const float* __restrict__ sDeg, float4* __restrict__ out_chi,
    int base, int tid, int N)
{
    float4* chi = out_chi + (size_t)base * 72;
    int nres = N - base;
    if (nres > ABLK) nres = ABLK;
    const int groupsTotal = nres * 72;

    int v    = tid;
    int rowl = tid / 18;
    int grp  = tid - rowl * 18;
    #pragma unroll 1
    for (; v < groupsTotal; v += ABLK) {
        float deg = sDeg[rowl];
        float cbase = -180.0f + 20.0f * (float)grp;
        float r0, r1, r2, r3;
        {
            float ad = fabsf(deg - cbase);
            float dw = fminf(ad, 360.0f - ad);
            r0 = __expf(-0.08f * dw * dw);
        }
        {
            float ad = fabsf(deg - (cbase + 5.0f));
            float dw = fminf(ad, 360.0f - ad);
            r1 = __expf(-0.08f * dw * dw);
        }
        {
            float ad = fabsf(deg - (cbase + 10.0f));
            float dw = fminf(ad, 360.0f - ad);
            r2 = __expf(-0.08f * dw * dw);
        }
        {
            float ad = fabsf(deg - (cbase + 15.0f));
            float dw = fminf(ad, 360.0f - ad);
            r3 = __expf(-0.08f * dw * dw);
        }
        __stcs(&chi[v], make_float4(r0, r1, r2, r3));

        grp  += 2;
        rowl += 7;
        if (grp >= 18) { grp -= 18; ++rowl; }
    }
}

// ---------------------------------------------------------------------------
// Fused kernel with phase-parity scheduling (per-block uniform branches).
// __launch_bounds__(128, 8): cap regs at 64 -> 8 blocks/SM.
// ---------------------------------------------------------------------------
__global__ void __launch_bounds__(ABLK, 8) fused_kernel(
    const float* __restrict__ fixedp,
    const float* __restrict__ mobilep,
    const float* __restrict__ coords,
    const float* __restrict__ prev,
    const float* __restrict__ bl,
    const float* __restrict__ ban,
    const float* __restrict__ dih,
    const float* __restrict__ degrees,
    float* __restrict__ out_aligned,   // N*45
    float* __restrict__ out_next,      // N*3
    float4* __restrict__ out_chi,      // N*72 float4
    int N)
{
    __shared__ float sDeg[ABLK * 4];
    __shared__ float sAT[ABLK][13];
    __shared__ float sC[64 * 45];      // staging buffer (2880 floats), reused by chi (needs 2304)

    const int tid  = threadIdx.x;
    const int base = blockIdx.x * ABLK;
    const int res  = base + tid;
    const bool fullBlock = (N - base) >= ABLK;

    // ---- coalesced staging of degrees ----
    {
        const size_t b4 = (size_t)base * 4;
        const int lim4 = N * 4 - (int)b4;
        #pragma unroll
        for (int k = 0; k < 4; ++k) {
            int idx = k * ABLK + tid;
            if (idx < lim4) sDeg[idx] = degrees[b4 + idx];
        }
    }
    __syncthreads();

    if ((blockIdx.x & 1) == 0) {
        // store-stream first
        if (fullBlock)
            phase_chi_windowed(sDeg, sC, out_chi, base, tid);
        else
            phase_chi_scalar(sDeg, out_chi, base, tid, N);
        phase_kabsch_nerf(fixedp, mobilep, prev, bl, ban, dih,
                          out_next, sAT, res, tid, N);
        __syncthreads();
        if (fullBlock)
            phase_transform_staged(coords, out_aligned, sAT, sC, base, tid);
        else
            phase_transform_scalar(coords, out_aligned, sAT, base, tid, N);
    } else {
        // ALU first
        phase_kabsch_nerf(fixedp, mobilep, prev, bl, ban, dih,
                          out_next, sAT, res, tid, N);
        __syncthreads();
        if (fullBlock) {
            phase_transform_staged(coords, out_aligned, sAT, sC, base, tid);
            __syncthreads();   // sC reuse: transform out done before chi zeros it
            phase_chi_windowed(sDeg, sC, out_chi, base, tid);
        } else {
            phase_transform_scalar(coords, out_aligned, sAT, base, tid, N);
            phase_chi_scalar(sDeg, out_chi, base, tid, N);
        }
    }
}

// ---------------------------------------------------------------------------
// Launch
// ---------------------------------------------------------------------------
extern "C" void kernel_launch(void* const* d_in, const int* in_sizes, int n_in,
                              void* d_out, int out_size)
{
    const float* fixedp  = (const float*)d_in[0];
    const float* mobilep = (const float*)d_in[1];
    const float* coords  = (const float*)d_in[2];
    const float* prev    = (const float*)d_in[3];
    const float* bl      = (const float*)d_in[4];
    const float* ban     = (const float*)d_in[5];
    const float* dih     = (const float*)d_in[6];
    const float* degrees = (const float*)d_in[7];

    const int N = in_sizes[4];  // bond_lengths is (N,1)

    float* out         = (float*)d_out;
    float* out_aligned = out;                       // N*45
    float* out_next    = out + (size_t)N * 45;      // N*3
    float* out_chi     = out + (size_t)N * 48;      // N*288 (16B aligned)

    fused_kernel<<<(N + ABLK - 1) / ABLK, ABLK>>>(
        fixedp, mobilep, coords, prev, bl, ban, dih, degrees,
        out_aligned, out_next, (float4*)out_chi, N);
}